// round 2
// baseline (speedup 1.0000x reference)
#include <cuda_runtime.h>
#include <math.h>

// SCPDTLoss on GB300/B200 (sm_100a/sm_103a)
//
// Math reduction: with w = 1/sigma, q = sqrt(w), A = [q*V | q*r] (d x 17),
// the lower triangle of G = A^T A contains:
//   G[k][j], k,j<16  -> V^T D^-1 V          (136 entries)
//   G[16][j], j<16   -> u = V^T D^-1 r      (16 entries)
//   G[16][16]        -> r^T D^-1 r          (1 entry)
// quad_form = rDr - ||L^{-1} u||^2  (M = G_vv + (1+jitter) I = L L^T)
// so only ONE pass over V and ONE forward solve are needed.
//
// Phase 1: per-patch streaming Gram + stats   (512 CTAs x 256 thr)
// Phase 2: per-patch 16x16 Cholesky + solve   (2 CTAs x 256 thr)
// Phase 3: boundary loss (14 boundaries)      (14 CTAs x 256 thr)
// Phase 4: final combine -> 7 outputs         (1 CTA x 256 thr)

#define NPATCH 512
#define DDIM   12288
#define TPB    256
#define NITER  48            // DDIM / TPB

// scratch rows: 0..152 Gram tri, 153 sum(log sigma), 154 sum(sigma),
// 155 sum(relu(0.3-sigma)^2), 156 sum(V^2), 157 min(sigma)
__device__ float g_scr[158 * NPATCH];
__device__ float g_nll[NPATCH];
__device__ float g_bnd[14];

__global__ __launch_bounds__(TPB, 1) void phase1_kernel(
    const float* __restrict__ x0, const float* __restrict__ mu,
    const float* __restrict__ sigma, const float* __restrict__ V)
{
    const int p = blockIdx.x;
    const int t = threadIdx.x;
    const int b  = p >> 6;
    const int n  = p & 63;
    const int gy = n >> 3;
    const int gx = n & 7;

    const size_t pofs = (size_t)p * DDIM;
    const float4* __restrict__ Vp = (const float4*)(V + pofs * 16);
    const float*  __restrict__ sp = sigma + pofs;
    const float*  __restrict__ mp = mu + pofs;
    // x0 base for this patch + this thread's fixed px = t & 63
    const float* __restrict__ x0b =
        x0 + (size_t)b * (3 * 512 * 512) + (size_t)(gy * 64) * 512 + gx * 64 + (t & 63);
    const int t0 = t >> 6;   // d>>6 = 4*i + t0

    float acc[157];
#pragma unroll
    for (int i = 0; i < 157; i++) acc[i] = 0.0f;
    float smin = 3.402823466e38f;

#pragma unroll 2
    for (int i = 0; i < NITER; i++) {
        const int d = i * TPB + t;
        const float4 va = Vp[d * 4 + 0];
        const float4 vb = Vp[d * 4 + 1];
        const float4 vc = Vp[d * 4 + 2];
        const float4 vd = Vp[d * 4 + 3];
        const float s = sp[d];
        const float m = mp[d];
        const int rr = i * 4 + t0;                       // = d >> 6
        const float x = x0b[(rr >> 6) * (512 * 512) + (rr & 63) * 512];

        const float q = rsqrtf(s);
        const float r = x - m;

        float a[17];
        a[0]  = q * va.x; a[1]  = q * va.y; a[2]  = q * va.z; a[3]  = q * va.w;
        a[4]  = q * vb.x; a[5]  = q * vb.y; a[6]  = q * vb.z; a[7]  = q * vb.w;
        a[8]  = q * vc.x; a[9]  = q * vc.y; a[10] = q * vc.z; a[11] = q * vc.w;
        a[12] = q * vd.x; a[13] = q * vd.y; a[14] = q * vd.z; a[15] = q * vd.w;
        a[16] = q * r;

#pragma unroll
        for (int k = 0; k < 17; k++) {
#pragma unroll
            for (int j = 0; j <= k; j++) {
                const int idx = k * (k + 1) / 2 + j;
                acc[idx] = fmaf(a[k], a[j], acc[idx]);
            }
        }

        acc[153] += __logf(s);
        acc[154] += s;
        const float rl = fmaxf(0.3f - s, 0.0f);
        acc[155] = fmaf(rl, rl, acc[155]);

        float vsq = va.x * va.x;
        vsq = fmaf(va.y, va.y, vsq); vsq = fmaf(va.z, va.z, vsq); vsq = fmaf(va.w, va.w, vsq);
        vsq = fmaf(vb.x, vb.x, vsq); vsq = fmaf(vb.y, vb.y, vsq); vsq = fmaf(vb.z, vb.z, vsq);
        vsq = fmaf(vb.w, vb.w, vsq);
        vsq = fmaf(vc.x, vc.x, vsq); vsq = fmaf(vc.y, vc.y, vsq); vsq = fmaf(vc.z, vc.z, vsq);
        vsq = fmaf(vc.w, vc.w, vsq);
        vsq = fmaf(vd.x, vd.x, vsq); vsq = fmaf(vd.y, vd.y, vsq); vsq = fmaf(vd.z, vd.z, vsq);
        vsq = fmaf(vd.w, vd.w, vsq);
        acc[156] += vsq;

        smin = fminf(smin, s);
    }

    // intra-warp butterfly reduce
#pragma unroll
    for (int o = 16; o > 0; o >>= 1) {
#pragma unroll
        for (int idx = 0; idx < 157; idx++)
            acc[idx] += __shfl_xor_sync(0xffffffffu, acc[idx], o);
        smin = fminf(smin, __shfl_xor_sync(0xffffffffu, smin, o));
    }

    __shared__ float red[8][158];
    const int w = t >> 5, lane = t & 31;
    if (lane == 0) {
#pragma unroll
        for (int idx = 0; idx < 157; idx++) red[w][idx] = acc[idx];
        red[w][157] = smin;
    }
    __syncthreads();

    if (t < 158) {
        float v = red[0][t];
        if (t == 157) {
#pragma unroll
            for (int ww = 1; ww < 8; ww++) v = fminf(v, red[ww][t]);
        } else {
#pragma unroll
            for (int ww = 1; ww < 8; ww++) v += red[ww][t];
        }
        g_scr[t * NPATCH + p] = v;
    }
}

// One thread per patch: 16x16 Cholesky + forward solve, fully unrolled.
__global__ __launch_bounds__(256, 1) void phase2_kernel()
{
    const int p = blockIdx.x * 256 + threadIdx.x;

    float L[136];
#pragma unroll
    for (int i = 0; i < 136; i++) L[i] = g_scr[i * NPATCH + p];
    float u[16];
#pragma unroll
    for (int j = 0; j < 16; j++) u[j] = g_scr[(136 + j) * NPATCH + p];
    const float rDr     = g_scr[152 * NPATCH + p];
    const float logdetD = g_scr[153 * NPATCH + p];

#pragma unroll
    for (int k = 0; k < 16; k++) L[k * (k + 1) / 2 + k] += 1.000001f;  // (1+jitter) I

    float invd[16];
    float logdetM = 0.0f;
#pragma unroll
    for (int k = 0; k < 16; k++) {
#pragma unroll
        for (int j = 0; j < k; j++) {
            float sum = L[k * (k + 1) / 2 + j];
#pragma unroll
            for (int i2 = 0; i2 < j; i2++)
                sum -= L[k * (k + 1) / 2 + i2] * L[j * (j + 1) / 2 + i2];
            L[k * (k + 1) / 2 + j] = sum * invd[j];
        }
        float sum = L[k * (k + 1) / 2 + k];
#pragma unroll
        for (int i2 = 0; i2 < k; i2++)
            sum -= L[k * (k + 1) / 2 + i2] * L[k * (k + 1) / 2 + i2];
        const float lkk = sqrtf(sum);
        invd[k] = 1.0f / lkk;
        logdetM += 2.0f * __logf(lkk);
    }

    // quad correction = || L^{-1} u ||^2
    float y[16];
    float corr = 0.0f;
#pragma unroll
    for (int k = 0; k < 16; k++) {
        float sum = u[k];
#pragma unroll
        for (int j = 0; j < k; j++) sum -= L[k * (k + 1) / 2 + j] * y[j];
        y[k] = sum * invd[k];
        corr = fmaf(y[k], y[k], corr);
    }

    const float quad = rDr - corr;
    const float GC = 12288.0f * 1.8378770664093453f;   // d * log(2*pi)
    g_nll[p] = 0.5f * (quad + logdetD + logdetM + GC) * (1.0f / 12288.0f);
}

// Boundary loss: blocks 0..6 -> dy at y = 64*(j+1); blocks 7..13 -> dx at x = 64*(j-6).
__global__ __launch_bounds__(256) void phase3_kernel(const float* __restrict__ mu)
{
    const int j = blockIdx.x;
    const int t = threadIdx.x;
    const bool isdy = (j < 7);
    const int J = isdy ? (j + 1) : (j - 6);

    float sum = 0.0f;
    for (int e = t; e < 12288; e += 256) {
        const int b   = e / 1536;
        const int rem = e - b * 1536;
        const int c   = rem >> 9;       // channel
        const int pos = rem & 511;      // x (dy) or y (dx)
        const int g   = pos >> 6;
        const int q   = pos & 63;
        float hi, lo;
        if (isdy) {
            hi = mu[(size_t)(b * 64 + J * 8 + g) * 12288 + c * 4096 + q];              // py=0
            lo = mu[(size_t)(b * 64 + (J - 1) * 8 + g) * 12288 + c * 4096 + 4032 + q]; // py=63
        } else {
            hi = mu[(size_t)(b * 64 + g * 8 + J) * 12288 + c * 4096 + q * 64];         // px=0
            lo = mu[(size_t)(b * 64 + g * 8 + J - 1) * 12288 + c * 4096 + q * 64 + 63];// px=63
        }
        const float dd = hi - lo;
        sum = fmaf(dd, dd, sum);
    }

    __shared__ float sred[256];
    sred[t] = sum;
    __syncthreads();
    for (int s = 128; s > 0; s >>= 1) {
        if (t < s) sred[t] += sred[t + s];
        __syncthreads();
    }
    if (t == 0) g_bnd[j] = sred[0] * (1.0f / 12288.0f);
}

__global__ __launch_bounds__(256) void phase4_kernel(float* __restrict__ out)
{
    const int t = threadIdx.x;
    float nll  = g_nll[t] + g_nll[t + 256];
    float ssum = g_scr[154 * NPATCH + t] + g_scr[154 * NPATCH + t + 256];
    float srel = g_scr[155 * NPATCH + t] + g_scr[155 * NPATCH + t + 256];
    float sv2  = g_scr[156 * NPATCH + t] + g_scr[156 * NPATCH + t + 256];
    float smin = fminf(g_scr[157 * NPATCH + t], g_scr[157 * NPATCH + t + 256]);

    __shared__ float r0[256], r1[256], r2[256], r3[256], r4[256];
    r0[t] = nll; r1[t] = ssum; r2[t] = srel; r3[t] = sv2; r4[t] = smin;
    __syncthreads();
    for (int s = 128; s > 0; s >>= 1) {
        if (t < s) {
            r0[t] += r0[t + s];
            r1[t] += r1[t + s];
            r2[t] += r2[t + s];
            r3[t] += r3[t + s];
            r4[t]  = fminf(r4[t], r4[t + s]);
        }
        __syncthreads();
    }

    if (t == 0) {
        const float recon = r0[0] * (1.0f / 512.0f);
        float bnd = 0.0f;
#pragma unroll
        for (int jj = 0; jj < 14; jj++) bnd += g_bnd[jj];
        bnd *= (1.0f / 14.0f);
        const float rank = r3[0] * (1.0f / (512.0f * 12288.0f * 16.0f));
        const float sigp = r2[0] * (1.0f / (512.0f * 12288.0f));
        const float msig = r1[0] * (1.0f / (512.0f * 12288.0f));
        const float total = recon + 0.1f * bnd + 0.01f * rank + 0.05f * sigp;
        out[0] = total;
        out[1] = recon;
        out[2] = bnd;
        out[3] = rank;
        out[4] = sigp;
        out[5] = msig;
        out[6] = r4[0];
    }
}

extern "C" void kernel_launch(void* const* d_in, const int* in_sizes, int n_in,
                              void* d_out, int out_size)
{
    const float* x0    = (const float*)d_in[0];
    const float* mu    = (const float*)d_in[1];
    const float* sigma = (const float*)d_in[2];
    const float* V     = (const float*)d_in[3];
    float* out = (float*)d_out;

    phase1_kernel<<<NPATCH, TPB>>>(x0, mu, sigma, V);
    phase2_kernel<<<2, 256>>>();
    phase3_kernel<<<14, 256>>>(mu);
    phase4_kernel<<<1, 256>>>(out);
}